// round 13
// baseline (speedup 1.0000x reference)
#include <cuda_runtime.h>
#include <cuda_fp16.h>
#include <cuda_bf16.h>
#include <cstdint>

// Problem constants (match reference_code)
#define N_NODES   100000
#define IN_DIM    256
#define OUT_DIM   64
#define KEEP_INV  (1.0f / 0.9f)
#define NBLK      ((N_NODES + 255) / 256)   // 391

// Padded-segment strides. Counts: x rows ~ Poisson(14.4) (P(>=64) ~1e-20),
// adj rows ~ Poisson(32) (P(>=96) ~1e-18 over all rows). Clamped defensively.
#define XSTRIDE   64
#define ASTRIDE   96

// ---------------------------------------------------------------------------
// Scratch (static device globals; no runtime allocation).  ~142 MB total.
// h is fp16: spmm2's gather rides L1/L2 at half the fp32 footprint.
// ---------------------------------------------------------------------------
__device__ __align__(16) __half g_h[N_NODES * OUT_DIM];          // 12.8 MB
__device__ int  g_xcnt[N_NODES], g_acnt[N_NODES];
__device__ __align__(16) int2 g_pax[N_NODES * XSTRIDE];          // 51.2 MB
__device__ __align__(16) int2 g_paa[N_NODES * ASTRIDE];          // 76.8 MB

// ---------------------------------------------------------------------------
// 1) Zero per-row counters.
// ---------------------------------------------------------------------------
__global__ void zero_cnt_kernel() {
    int i = blockIdx.x * blockDim.x + threadIdx.x;
    if (i < N_NODES) { g_xcnt[i] = 0; g_acnt[i] = 0; }
}

// ---------------------------------------------------------------------------
// 2) FUSED CSR build: one pass. The count atomic's return value is the
//    element's final slot within its row's fixed-stride segment.
//    Blocks [0, xblocks) handle x; the rest handle adj.
// ---------------------------------------------------------------------------
__global__ void __launch_bounds__(256) build_kernel(
        const float* __restrict__ x_vals, const int* __restrict__ x_rows,
        const int*   __restrict__ x_cols, const int* __restrict__ keep, int xnnz,
        const float* __restrict__ adj_vals, const int* __restrict__ adj_rows,
        const int*   __restrict__ adj_cols, int annz, int xblocks) {
    if ((int)blockIdx.x < xblocks) {
        int base = blockIdx.x * 1024 + threadIdx.x;
        int row[4], col[4], kp[4]; float val[4];
        #pragma unroll
        for (int u = 0; u < 4; ++u) {           // independent streaming loads
            int i = base + u * 256;
            bool b = (i < xnnz);
            row[u] = b ? x_rows[i] : -1;
            kp[u]  = b ? keep[i]   : 0;
            col[u] = b ? x_cols[i] : 0;
            val[u] = b ? x_vals[i] : 0.f;
        }
        #pragma unroll
        for (int u = 0; u < 4; ++u) {
            if (row[u] >= 0 && kp[u] != 0) {
                int rk = atomicAdd(&g_xcnt[row[u]], 1);
                if (rk < XSTRIDE)
                    g_pax[row[u] * XSTRIDE + rk] =
                        make_int2(col[u], __float_as_int(val[u] * KEEP_INV));
            }
        }
    } else {
        int base = ((int)blockIdx.x - xblocks) * 1024 + threadIdx.x;
        int row[4], col[4]; float val[4];
        #pragma unroll
        for (int u = 0; u < 4; ++u) {
            int i = base + u * 256;
            bool b = (i < annz);
            row[u] = b ? adj_rows[i] : -1;
            col[u] = b ? adj_cols[i] : 0;
            val[u] = b ? adj_vals[i] : 0.f;
        }
        #pragma unroll
        for (int u = 0; u < 4; ++u) {
            if (row[u] >= 0) {
                int rk = atomicAdd(&g_acnt[row[u]], 1);
                if (rk < ASTRIDE)
                    g_paa[row[u] * ASTRIDE + rk] =
                        make_int2(col[u], __float_as_int(val[u]));
            }
        }
    }
}

// ---------------------------------------------------------------------------
// 3) SpMM1: one warp per node; lane t owns outputs [2t, 2t+1].
//    Broadcast-LDG inner loop (no shuffles): all lanes load the same edge
//    pair via int4 (one L1 broadcast wavefront), 4 edges per iteration.
// ---------------------------------------------------------------------------
__global__ void spmm1_csr_kernel(const float* __restrict__ W) {
    int warp = (blockIdx.x * blockDim.x + threadIdx.x) >> 5;
    int lane = threadIdx.x & 31;
    if (warp >= N_NODES) return;

    const float2* __restrict__ W2  = (const float2*)W;
    const int4*   __restrict__ seg = (const int4*)(g_pax + warp * XSTRIDE);
    int c = min(g_xcnt[warp], XSTRIDE);
    float2 acc = make_float2(0.f, 0.f);

    int npair = c >> 1;                         // edge pairs (int4 units)
    int p = 0;
    for (; p + 2 <= npair; p += 2) {            // 4 edges per iteration
        int4 eA = seg[p];
        int4 eB = seg[p + 1];
        float2 w0 = W2[eA.x * (OUT_DIM / 2) + lane];
        float2 w1 = W2[eA.z * (OUT_DIM / 2) + lane];
        float2 w2 = W2[eB.x * (OUT_DIM / 2) + lane];
        float2 w3 = W2[eB.z * (OUT_DIM / 2) + lane];
        float v0 = __int_as_float(eA.y), v1 = __int_as_float(eA.w);
        float v2 = __int_as_float(eB.y), v3 = __int_as_float(eB.w);
        acc.x = fmaf(v0, w0.x, acc.x); acc.y = fmaf(v0, w0.y, acc.y);
        acc.x = fmaf(v1, w1.x, acc.x); acc.y = fmaf(v1, w1.y, acc.y);
        acc.x = fmaf(v2, w2.x, acc.x); acc.y = fmaf(v2, w2.y, acc.y);
        acc.x = fmaf(v3, w3.x, acc.x); acc.y = fmaf(v3, w3.y, acc.y);
    }
    const int2* seg2 = (const int2*)seg;
    for (int j = p * 2; j < c; ++j) {           // tail (<= 3 edges)
        int2 e = seg2[j];
        float v = __int_as_float(e.y);
        float2 w = W2[e.x * (OUT_DIM / 2) + lane];
        acc.x = fmaf(v, w.x, acc.x);
        acc.y = fmaf(v, w.y, acc.y);
    }
    reinterpret_cast<__half2*>(g_h)[warp * (OUT_DIM / 2) + lane] = __float22half2_rn(acc);
}

// ---------------------------------------------------------------------------
// 4) SpMM2 + fused ReLU: one warp per node, broadcast-LDG inner loop.
//    out[n,:] = relu( sum_e a_e * h[col_e,:] )  (h fp16)
// ---------------------------------------------------------------------------
__global__ void spmm2_csr_kernel(float* __restrict__ out) {
    int warp = (blockIdx.x * blockDim.x + threadIdx.x) >> 5;
    int lane = threadIdx.x & 31;
    if (warp >= N_NODES) return;

    const __half2* __restrict__ hp  = (const __half2*)g_h;
    const int4*    __restrict__ seg = (const int4*)(g_paa + warp * ASTRIDE);
    int c = min(g_acnt[warp], ASTRIDE);
    float2 acc = make_float2(0.f, 0.f);

    int npair = c >> 1;
    int p = 0;
    for (; p + 2 <= npair; p += 2) {            // 4 edges per iteration
        int4 eA = seg[p];
        int4 eB = seg[p + 1];
        float2 h0 = __half22float2(hp[eA.x * (OUT_DIM / 2) + lane]);
        float2 h1 = __half22float2(hp[eA.z * (OUT_DIM / 2) + lane]);
        float2 h2 = __half22float2(hp[eB.x * (OUT_DIM / 2) + lane]);
        float2 h3 = __half22float2(hp[eB.z * (OUT_DIM / 2) + lane]);
        float v0 = __int_as_float(eA.y), v1 = __int_as_float(eA.w);
        float v2 = __int_as_float(eB.y), v3 = __int_as_float(eB.w);
        acc.x = fmaf(v0, h0.x, acc.x); acc.y = fmaf(v0, h0.y, acc.y);
        acc.x = fmaf(v1, h1.x, acc.x); acc.y = fmaf(v1, h1.y, acc.y);
        acc.x = fmaf(v2, h2.x, acc.x); acc.y = fmaf(v2, h2.y, acc.y);
        acc.x = fmaf(v3, h3.x, acc.x); acc.y = fmaf(v3, h3.y, acc.y);
    }
    const int2* seg2 = (const int2*)seg;
    for (int j = p * 2; j < c; ++j) {           // tail (<= 3 edges)
        int2 e = seg2[j];
        float v = __int_as_float(e.y);
        float2 hv = __half22float2(hp[e.x * (OUT_DIM / 2) + lane]);
        acc.x = fmaf(v, hv.x, acc.x);
        acc.y = fmaf(v, hv.y, acc.y);
    }
    acc.x = fmaxf(acc.x, 0.f);
    acc.y = fmaxf(acc.y, 0.f);
    reinterpret_cast<float2*>(out)[warp * (OUT_DIM / 2) + lane] = acc;
}

// ---------------------------------------------------------------------------
// Input order: 0 x_vals, 1 x_rows, 2 x_cols, 3 adj_vals, 4 adj_rows,
//              5 adj_cols, 6 W, 7 keep_mask(int32)
// ---------------------------------------------------------------------------
extern "C" void kernel_launch(void* const* d_in, const int* in_sizes, int n_in,
                              void* d_out, int out_size) {
    if (n_in < 8) return;

    const float* x_vals   = (const float*)d_in[0];
    const int*   x_rows   = (const int*)  d_in[1];
    const int*   x_cols   = (const int*)  d_in[2];
    const float* adj_vals = (const float*)d_in[3];
    const int*   adj_rows = (const int*)  d_in[4];
    const int*   adj_cols = (const int*)  d_in[5];
    const float* W        = (const float*)d_in[6];
    const int*   keep     = (const int*)  d_in[7];

    const int x_nnz = in_sizes[0];
    const int a_nnz = in_sizes[3];
    float* out = (float*)d_out;

    const int T = 256;
    int xblocks = (x_nnz + 1023) / 1024;        // 4 elements per thread
    int ablocks = (a_nnz + 1023) / 1024;

    // Fused CSR build (2 launches total before the SpMMs)
    zero_cnt_kernel<<<NBLK, T>>>();
    build_kernel<<<xblocks + ablocks, T>>>(x_vals, x_rows, x_cols, keep, x_nnz,
                                           adj_vals, adj_rows, adj_cols, a_nnz,
                                           xblocks);

    // Gather-reduce SpMMs (one warp per node; 8 warps per block)
    int warp_blocks = (N_NODES * 32 + T - 1) / T;
    spmm1_csr_kernel<<<warp_blocks, T>>>(W);
    spmm2_csr_kernel<<<warp_blocks, T>>>(out);
}

// round 15
// speedup vs baseline: 1.2316x; 1.2316x over previous
#include <cuda_runtime.h>
#include <cuda_fp16.h>
#include <cuda_bf16.h>
#include <cstdint>

// Problem constants (match reference_code)
#define N_NODES   100000
#define IN_DIM    256
#define OUT_DIM   64
#define KEEP_INV  (1.0f / 0.9f)
#define NBLK      ((N_NODES + 255) / 256)   // 391

// Padded-segment strides. Counts: x rows ~ Poisson(14.4) (P(>=64) ~1e-20),
// adj rows ~ Poisson(32) (P(>=96) ~1e-18 over all rows). Clamped defensively.
#define XSTRIDE   64
#define ASTRIDE   96

// ---------------------------------------------------------------------------
// Scratch (static device globals; no runtime allocation).  ~142 MB total.
// h is fp16: halves the spmm2 gather wavefronts vs fp32.
// ---------------------------------------------------------------------------
__device__ __align__(16) __half g_h[N_NODES * OUT_DIM];          // 12.8 MB
__device__ int  g_xcnt[N_NODES], g_acnt[N_NODES];
__device__ __align__(16) int2 g_pax[N_NODES * XSTRIDE];          // 51.2 MB
__device__ __align__(16) int2 g_paa[N_NODES * ASTRIDE];          // 76.8 MB

// ---------------------------------------------------------------------------
// 1) Zero per-row counters.
// ---------------------------------------------------------------------------
__global__ void zero_cnt_kernel() {
    int i = blockIdx.x * blockDim.x + threadIdx.x;
    if (i < N_NODES) { g_xcnt[i] = 0; g_acnt[i] = 0; }
}

// ---------------------------------------------------------------------------
// 2) FUSED CSR build: one pass. The count atomic's return value is the
//    element's final slot within its row's fixed-stride segment.
//    Blocks [0, xblocks) handle x; the rest handle adj.
// ---------------------------------------------------------------------------
__global__ void __launch_bounds__(256) build_kernel(
        const float* __restrict__ x_vals, const int* __restrict__ x_rows,
        const int*   __restrict__ x_cols, const int* __restrict__ keep, int xnnz,
        const float* __restrict__ adj_vals, const int* __restrict__ adj_rows,
        const int*   __restrict__ adj_cols, int annz, int xblocks) {
    if ((int)blockIdx.x < xblocks) {
        int base = blockIdx.x * 1024 + threadIdx.x;
        int row[4], col[4], kp[4]; float val[4];
        #pragma unroll
        for (int u = 0; u < 4; ++u) {           // independent streaming loads
            int i = base + u * 256;
            bool b = (i < xnnz);
            row[u] = b ? x_rows[i] : -1;
            kp[u]  = b ? keep[i]   : 0;
            col[u] = b ? x_cols[i] : 0;
            val[u] = b ? x_vals[i] : 0.f;
        }
        #pragma unroll
        for (int u = 0; u < 4; ++u) {
            if (row[u] >= 0 && kp[u] != 0) {
                int rk = atomicAdd(&g_xcnt[row[u]], 1);
                if (rk < XSTRIDE)
                    g_pax[row[u] * XSTRIDE + rk] =
                        make_int2(col[u], __float_as_int(val[u] * KEEP_INV));
            }
        }
    } else {
        int base = ((int)blockIdx.x - xblocks) * 1024 + threadIdx.x;
        int row[4], col[4]; float val[4];
        #pragma unroll
        for (int u = 0; u < 4; ++u) {
            int i = base + u * 256;
            bool b = (i < annz);
            row[u] = b ? adj_rows[i] : -1;
            col[u] = b ? adj_cols[i] : 0;
            val[u] = b ? adj_vals[i] : 0.f;
        }
        #pragma unroll
        for (int u = 0; u < 4; ++u) {
            if (row[u] >= 0) {
                int rk = atomicAdd(&g_acnt[row[u]], 1);
                if (rk < ASTRIDE)
                    g_paa[row[u] * ASTRIDE + rk] =
                        make_int2(col[u], __float_as_int(val[u]));
            }
        }
    }
}

// ---------------------------------------------------------------------------
// 3) SpMM1: one warp per node; lane t owns outputs [2t, 2t+1].
//    Chunked smem-staged edges: warp stages 32 (col,val) pairs coalesced,
//    inner loop reads each via one broadcast LDS.64 (no shuffles).
// ---------------------------------------------------------------------------
__global__ void __launch_bounds__(256) spmm1_csr_kernel(const float* __restrict__ W) {
    __shared__ int2 stage[8][32];
    int wib  = threadIdx.x >> 5;                // warp index in block
    int warp = (blockIdx.x * blockDim.x + threadIdx.x) >> 5;
    int lane = threadIdx.x & 31;
    if (warp >= N_NODES) return;

    const float2* __restrict__ W2  = (const float2*)W;
    const int2*   __restrict__ seg = g_pax + warp * XSTRIDE;
    int c = min(g_xcnt[warp], XSTRIDE);
    float2 acc = make_float2(0.f, 0.f);

    for (int base = 0; base < c; base += 32) {
        int idx = base + lane;
        stage[wib][lane] = (idx < c) ? seg[idx] : make_int2(0, 0);
        __syncwarp();
        int m = min(32, c - base);
        if (m == 32) {
            #pragma unroll
            for (int j = 0; j < 32; ++j) {
                int2 e = stage[wib][j];
                float v = __int_as_float(e.y);
                float2 w = W2[e.x * (OUT_DIM / 2) + lane];
                acc.x = fmaf(v, w.x, acc.x);
                acc.y = fmaf(v, w.y, acc.y);
            }
        } else {
            for (int j = 0; j < m; ++j) {
                int2 e = stage[wib][j];
                float v = __int_as_float(e.y);
                float2 w = W2[e.x * (OUT_DIM / 2) + lane];
                acc.x = fmaf(v, w.x, acc.x);
                acc.y = fmaf(v, w.y, acc.y);
            }
        }
        __syncwarp();
    }
    reinterpret_cast<__half2*>(g_h)[warp * (OUT_DIM / 2) + lane] = __float22half2_rn(acc);
}

// ---------------------------------------------------------------------------
// 4) SpMM2 + fused ReLU: same smem-staged structure; h fp16 gather.
//    out[n,:] = relu( sum_e a_e * h[col_e,:] )
// ---------------------------------------------------------------------------
__global__ void __launch_bounds__(256) spmm2_csr_kernel(float* __restrict__ out) {
    __shared__ int2 stage[8][32];
    int wib  = threadIdx.x >> 5;
    int warp = (blockIdx.x * blockDim.x + threadIdx.x) >> 5;
    int lane = threadIdx.x & 31;
    if (warp >= N_NODES) return;

    const __half2* __restrict__ hp  = (const __half2*)g_h;
    const int2*    __restrict__ seg = g_paa + warp * ASTRIDE;
    int c = min(g_acnt[warp], ASTRIDE);
    float2 acc = make_float2(0.f, 0.f);

    for (int base = 0; base < c; base += 32) {
        int idx = base + lane;
        stage[wib][lane] = (idx < c) ? seg[idx] : make_int2(0, 0);
        __syncwarp();
        int m = min(32, c - base);
        if (m == 32) {
            #pragma unroll
            for (int j = 0; j < 32; ++j) {
                int2 e = stage[wib][j];
                float v = __int_as_float(e.y);
                float2 hv = __half22float2(hp[e.x * (OUT_DIM / 2) + lane]);
                acc.x = fmaf(v, hv.x, acc.x);
                acc.y = fmaf(v, hv.y, acc.y);
            }
        } else {
            for (int j = 0; j < m; ++j) {
                int2 e = stage[wib][j];
                float v = __int_as_float(e.y);
                float2 hv = __half22float2(hp[e.x * (OUT_DIM / 2) + lane]);
                acc.x = fmaf(v, hv.x, acc.x);
                acc.y = fmaf(v, hv.y, acc.y);
            }
        }
        __syncwarp();
    }
    acc.x = fmaxf(acc.x, 0.f);
    acc.y = fmaxf(acc.y, 0.f);
    reinterpret_cast<float2*>(out)[warp * (OUT_DIM / 2) + lane] = acc;
}

// ---------------------------------------------------------------------------
// Input order: 0 x_vals, 1 x_rows, 2 x_cols, 3 adj_vals, 4 adj_rows,
//              5 adj_cols, 6 W, 7 keep_mask(int32)
// ---------------------------------------------------------------------------
extern "C" void kernel_launch(void* const* d_in, const int* in_sizes, int n_in,
                              void* d_out, int out_size) {
    if (n_in < 8) return;

    const float* x_vals   = (const float*)d_in[0];
    const int*   x_rows   = (const int*)  d_in[1];
    const int*   x_cols   = (const int*)  d_in[2];
    const float* adj_vals = (const float*)d_in[3];
    const int*   adj_rows = (const int*)  d_in[4];
    const int*   adj_cols = (const int*)  d_in[5];
    const float* W        = (const float*)d_in[6];
    const int*   keep     = (const int*)  d_in[7];

    const int x_nnz = in_sizes[0];
    const int a_nnz = in_sizes[3];
    float* out = (float*)d_out;

    const int T = 256;
    int xblocks = (x_nnz + 1023) / 1024;        // 4 elements per thread
    int ablocks = (a_nnz + 1023) / 1024;

    // Fused CSR build (2 launches total before the SpMMs)
    zero_cnt_kernel<<<NBLK, T>>>();
    build_kernel<<<xblocks + ablocks, T>>>(x_vals, x_rows, x_cols, keep, x_nnz,
                                           adj_vals, adj_rows, adj_cols, a_nnz,
                                           xblocks);

    // Gather-reduce SpMMs (one warp per node; 8 warps per block)
    int warp_blocks = (N_NODES * 32 + T - 1) / T;
    spmm1_csr_kernel<<<warp_blocks, T>>>(W);
    spmm2_csr_kernel<<<warp_blocks, T>>>(out);
}